// round 7
// baseline (speedup 1.0000x reference)
#include <cuda_runtime.h>
#include <cuda_fp16.h>
#include <cstdint>

// ---------------------------------------------------------------- shapes
#define BATCH 4
#define SEQ   4096
#define DIM   1024
#define MM    (BATCH * SEQ)   // 16384
#define KK    DIM             // 1024
#define NN    (4 * DIM)       // 4096 : interleaved [q k v g] per dim

// GEMM tiling
#define BM 128
#define BN 256
#define BK 32
#define KITERS (KK / BK)      // 32
// scan chunking: one GEMM M-block == one chunk
#define NCHUNK_S 32
#define CHUNK_S  128

// ---------------------------------------------------------------- scratch
static __device__ __half g_Ahi[(size_t)MM * KK];
static __device__ __half g_Alo[(size_t)MM * KK];
static __device__ __half g_Wh [(size_t)NN * KK];    // column-permuted: e' = 4d+j
static __device__ float  g_ball[NN];                 // permuted bias
static __device__ float  g_q [(size_t)MM * DIM];
static __device__ float  g_kv[(size_t)MM * DIM];
static __device__ float  g_gs[(size_t)MM * DIM];
static __device__ float  g_part[BATCH * NCHUNK_S * DIM];

// ---------------------------------------------------------------- helpers
__device__ __forceinline__ uint32_t smem_u32(const void* p) {
    uint32_t a;
    asm("{ .reg .u64 t; cvta.to.shared.u64 t, %1; cvt.u32.u64 %0, t; }" : "=r"(a) : "l"(p));
    return a;
}

__device__ __forceinline__ void cp_async16(uint32_t smem_addr, const void* gptr) {
    asm volatile("cp.async.cg.shared.global [%0], [%1], 16;"
                 :: "r"(smem_addr), "l"(gptr) : "memory");
}
#define CP_COMMIT() asm volatile("cp.async.commit_group;" ::: "memory")
#define CP_WAIT1()  asm volatile("cp.async.wait_group 1;" ::: "memory")
#define CP_WAIT0()  asm volatile("cp.async.wait_group 0;" ::: "memory")

__device__ __forceinline__ void ldm_x4(uint32_t* r, uint32_t addr) {
    asm volatile("ldmatrix.sync.aligned.m8n8.x4.shared.b16 {%0,%1,%2,%3}, [%4];"
                 : "=r"(r[0]), "=r"(r[1]), "=r"(r[2]), "=r"(r[3]) : "r"(addr));
}

__device__ __forceinline__ void mma16816(float* c, const uint32_t* a, const uint32_t* b) {
    asm volatile(
        "mma.sync.aligned.m16n8k16.row.col.f32.f16.f16.f32 "
        "{%0,%1,%2,%3}, {%4,%5,%6,%7}, {%8,%9}, {%0,%1,%2,%3};"
        : "+f"(c[0]), "+f"(c[1]), "+f"(c[2]), "+f"(c[3])
        : "r"(a[0]), "r"(a[1]), "r"(a[2]), "r"(a[3]), "r"(b[0]), "r"(b[1]));
}

// ---------------------------------------------------------------- conversion
__global__ __launch_bounds__(256)
void conv_x_kernel(const float* __restrict__ x)
{
    size_t i = (size_t)blockIdx.x * 256 + threadIdx.x;   // float4 index
    float4 v = ((const float4*)x)[i];
    size_t o = i * 4;
    float a[4] = {v.x, v.y, v.z, v.w};
#pragma unroll
    for (int j = 0; j < 4; j++) {
        __half h = __float2half_rn(a[j]);
        __half l = __float2half_rn(a[j] - __half2float(h));
        g_Ahi[o + j] = h;
        g_Alo[o + j] = l;
    }
}

// Permuted W: destination column e' = 4d + j, j in {0:q, 1:k, 2:v, 3:gate}.
__global__ __launch_bounds__(256)
void conv_w_kernel(const float* __restrict__ Wqkv, const float* __restrict__ bqkv,
                   const float* __restrict__ Wg,   const float* __restrict__ bg)
{
    int ep = blockIdx.x;                 // [0, NN) permuted col
    int d  = ep >> 2;
    int j  = ep & 3;
    int t  = threadIdx.x;                // 256 threads -> KK/4 float4 per row
    const float* src = (j < 3) ? (Wqkv + (size_t)(j * DIM + d) * KK)
                               : (Wg + (size_t)d * KK);
    float4 v = ((const float4*)src)[t];
    size_t o = (size_t)ep * KK + t * 4;
    g_Wh[o + 0] = __float2half_rn(v.x);
    g_Wh[o + 1] = __float2half_rn(v.y);
    g_Wh[o + 2] = __float2half_rn(v.z);
    g_Wh[o + 3] = __float2half_rn(v.w);
    if (t == 0)
        g_ball[ep] = (j < 3) ? bqkv[j * DIM + d] : bg[d];
}

// ---------------------------------------------------------------- GEMM
// SMEM: padded tiles [rows][40] fp16 (80 B row stride).
// Stage: Ahi(128r, 10240B) | Alo(128r, 10240B) | B(256r, 20480B) = 40960 B.
// 3 stages = 122880 B; epilogue reuses [0,128K) as C tile + 1 KB reduction.
#define TPAD 40
#define A_TILE_B (128 * TPAD * 2)        // 10240
#define B_TILE_B (256 * TPAD * 2)        // 20480
#define OFF_AHI 0
#define OFF_ALO (A_TILE_B)
#define OFF_B   (2 * A_TILE_B)
#define STAGE_B (2 * A_TILE_B + B_TILE_B)  // 40960
#define NSTAGE 3
#define GEMM_SMEM (128 * 256 * 4 + 1024)   // 132096 (>= 3*STAGE_B = 122880)

// Load a (rows x 32) fp16 tile: rows*4 16B chunks.
template<int ROWS, int PER_THREAD>
__device__ __forceinline__ void load_tile(uint32_t s_dst, const __half* g_src,
                                          int k0, int tid)
{
#pragma unroll
    for (int it = 0; it < PER_THREAD; it++) {
        int c   = tid + it * 256;        // [0, ROWS*4)
        int row = c >> 2;
        int kc  = c & 3;
        cp_async16(s_dst + (uint32_t)(row * (TPAD * 2) + kc * 16),
                   (const char*)(g_src + (size_t)row * KK + k0) + kc * 16);
    }
}

__device__ __forceinline__ void load_stage(uint32_t sbase, const __half* Ahi,
                                           const __half* Alo, const __half* Bh,
                                           int k0, int tid)
{
    load_tile<128, 2>(sbase + OFF_AHI, Ahi, k0, tid);
    load_tile<128, 2>(sbase + OFF_ALO, Alo, k0, tid);
    load_tile<256, 4>(sbase + OFF_B,   Bh,  k0, tid);
}

__global__ __launch_bounds__(256, 1)
void gemm_hmma_kernel()
{
    extern __shared__ char smem[];
    const uint32_t sb = smem_u32(smem);
    const int tid  = threadIdx.x;
    const int wid  = tid >> 5;
    const int lane = tid & 31;
    const int bm   = blockIdx.y;
    const int bn   = blockIdx.x;
    const int wM   = wid >> 2;           // 0..1  (M warp, 64 rows)
    const int wN   = wid & 3;            // 0..3  (N warp, 64 cols)

    const __half* Ahi = g_Ahi + (size_t)bm * BM * KK;
    const __half* Alo = g_Alo + (size_t)bm * BM * KK;
    const __half* Bh  = g_Wh  + (size_t)bn * BN * KK;

    float acc[4][8][4];                  // mi x ni x frag
#pragma unroll
    for (int i = 0; i < 4; i++)
#pragma unroll
        for (int j = 0; j < 8; j++)
#pragma unroll
            for (int r = 0; r < 4; r++) acc[i][j][r] = 0.0f;

    // ldmatrix lane addressing (verified R4-R6):
    const int aRow = wM * 64 + (lane & 15);
    const int aCol = (lane >> 4) * 8;
    const int bRowN = wN * 64 + ((lane >> 4) * 8) + (lane & 7);
    const int bColK = ((lane >> 3) & 1) * 8;

    // ---- prologue: stages 0,1
    load_stage(sb + 0 * STAGE_B, Ahi, Alo, Bh, 0, tid);
    CP_COMMIT();
    load_stage(sb + 1 * STAGE_B, Ahi, Alo, Bh, BK, tid);
    CP_COMMIT();

    int slot = 0, nslot = 2;
    for (int i = 0; i < KITERS; i++) {
        if (i < KITERS - 1) { CP_WAIT1(); } else { CP_WAIT0(); }
        __syncthreads();

        if (i + 2 < KITERS) {
            load_stage(sb + (uint32_t)nslot * STAGE_B, Ahi, Alo, Bh,
                       (i + 2) * BK, tid);
            CP_COMMIT();
        }

        const uint32_t cur = sb + (uint32_t)slot * STAGE_B;
#pragma unroll
        for (int ks = 0; ks < 2; ks++) {
            uint32_t ahi[4][4], alo[4][4], bf[8][2];
#pragma unroll
            for (int nh = 0; nh < 4; nh++) {
                uint32_t r[4];
                uint32_t boff = (uint32_t)((bRowN + nh * 16) * (TPAD * 2) +
                                           (ks * 16 + bColK) * 2);
                ldm_x4(r, cur + OFF_B + boff);
                bf[nh * 2 + 0][0] = r[0]; bf[nh * 2 + 0][1] = r[1];
                bf[nh * 2 + 1][0] = r[2]; bf[nh * 2 + 1][1] = r[3];
            }
#pragma unroll
            for (int mi = 0; mi < 4; mi++) {
                uint32_t aoff = (uint32_t)((aRow + mi * 16) * (TPAD * 2) +
                                           (ks * 16 + aCol) * 2);
                ldm_x4(ahi[mi], cur + OFF_AHI + aoff);
                ldm_x4(alo[mi], cur + OFF_ALO + aoff);
            }
#pragma unroll
            for (int mi = 0; mi < 4; mi++)
#pragma unroll
                for (int ni = 0; ni < 8; ni++)
                    mma16816(acc[mi][ni], ahi[mi], bf[ni]);
#pragma unroll
            for (int mi = 0; mi < 4; mi++)
#pragma unroll
                for (int ni = 0; ni < 8; ni++)
                    mma16816(acc[mi][ni], alo[mi], bf[ni]);
        }
        slot  = (slot == NSTAGE - 1) ? 0 : slot + 1;
        nslot = (nslot == NSTAGE - 1) ? 0 : nslot + 1;
    }

    // ---- fused epilogue ------------------------------------------------
    // Stage C tile (128x256 fp32, 128 KB) through smem; each thread then
    // processes 32 rows of one local dim (64 dims per CTA).
    __syncthreads();
    float* C = (float*)smem;
    const int g   = lane >> 2;
    const int tig = lane & 3;
#pragma unroll
    for (int mi = 0; mi < 4; mi++) {
#pragma unroll
        for (int ni = 0; ni < 8; ni++) {
            int col  = wN * 64 + ni * 8 + tig * 2;
            int row0 = wM * 64 + mi * 16 + g;
            C[row0 * 256 + col]           = acc[mi][ni][0];
            C[row0 * 256 + col + 1]       = acc[mi][ni][1];
            C[(row0 + 8) * 256 + col]     = acc[mi][ni][2];
            C[(row0 + 8) * 256 + col + 1] = acc[mi][ni][3];
        }
    }
    __syncthreads();

    const int dl = tid & 63;             // local dim 0..63
    const int rg = tid >> 6;             // row group 0..3 (32 rows each)
    const int dg = bn * 64 + dl;         // global dim
    const size_t m0 = (size_t)bm * BM;
    float4 bias = ((const float4*)g_ball)[bn * 64 + dl];
    float psum = 0.0f;
#pragma unroll 4
    for (int r = rg * 32; r < rg * 32 + 32; r++) {
        float4 c4 = ((const float4*)C)[r * 64 + dl];
        float qv = c4.x + bias.x;
        float kv = (c4.y + bias.y) * (c4.z + bias.z);
        float gt = c4.w + bias.w;
        float gs = 1.0f / (1.0f + __expf(-gt));
        size_t idx = (m0 + r) * DIM + dg;
        g_q [idx] = qv;
        g_kv[idx] = kv;
        g_gs[idx] = gs;
        psum += kv;
    }
    float* red = (float*)(smem + 128 * 256 * 4);
    red[rg * 64 + dl] = psum;
    __syncthreads();
    if (tid < 64) {
        float s = red[tid] + red[64 + tid] + red[128 + tid] + red[192 + tid];
        // bm = b*32 + chunk  ->  g_part[(b*NCHUNK_S + c)*DIM + d] = bm*DIM + d
        g_part[(size_t)bm * DIM + bn * 64 + tid] = s;
    }
}

// ---------------------------------------------------------------- scan phases
__global__ __launch_bounds__(256)
void scan_part_kernel()
{
    const int idx = blockIdx.x * 256 + threadIdx.x;
    const int b = idx / DIM;
    const int d = idx % DIM;
    float ex = 0.0f;
#pragma unroll
    for (int c = 0; c < NCHUNK_S; c++) {
        float t = g_part[(b * NCHUNK_S + c) * DIM + d];
        g_part[(b * NCHUNK_S + c) * DIM + d] = ex;
        ex += t;
    }
}

__global__ __launch_bounds__(256)
void final_kernel(float* __restrict__ out)
{
    const int d = blockIdx.x * 256 + threadIdx.x;
    const int c = blockIdx.y;
    const int b = blockIdx.z;
    float acc = g_part[(b * NCHUNK_S + c) * DIM + d];
    const size_t m0 = (size_t)(b * SEQ + c * CHUNK_S);
#pragma unroll 4
    for (int i = 0; i < CHUNK_S; i++) {
        size_t idx = (m0 + i) * DIM + d;
        acc += g_kv[idx];
        out[idx] = g_q[idx] * acc * g_gs[idx];
    }
}

// ---------------------------------------------------------------- launch
extern "C" void kernel_launch(void* const* d_in, const int* in_sizes, int n_in,
                              void* d_out, int out_size)
{
    const float* x    = (const float*)d_in[0];
    const float* Wqkv = (const float*)d_in[1];
    const float* bqkv = (const float*)d_in[2];
    const float* Wg   = (const float*)d_in[3];
    const float* bg   = (const float*)d_in[4];
    float* out        = (float*)d_out;

    conv_x_kernel<<<(MM * KK / 4) / 256, 256>>>(x);
    conv_w_kernel<<<NN, 256>>>(Wqkv, bqkv, Wg, bg);

    cudaFuncSetAttribute(gemm_hmma_kernel,
                         cudaFuncAttributeMaxDynamicSharedMemorySize, GEMM_SMEM);
    dim3 ggrid(NN / BN, MM / BM);          // (16, 128)
    gemm_hmma_kernel<<<ggrid, 256, GEMM_SMEM>>>();

    scan_part_kernel<<<(BATCH * DIM) / 256, 256>>>();
    dim3 fgrid(DIM / 256, NCHUNK_S, BATCH);
    final_kernel<<<fgrid, 256>>>(out);
}

// round 8
// speedup vs baseline: 1.0738x; 1.0738x over previous
#include <cuda_runtime.h>
#include <cuda_fp16.h>
#include <cstdint>

// ---------------------------------------------------------------- shapes
#define BATCH 4
#define SEQ   4096
#define DIM   1024
#define MM    (BATCH * SEQ)   // 16384
#define KK    DIM             // 1024
#define NN    (4 * DIM)       // 4096 : interleaved [q k v g] per dim

// GEMM tiling
#define BM 128
#define BN 128
#define BK 32
#define KITERS (KK / BK)      // 32
// scan chunking: one GEMM M-block == one chunk
#define NCHUNK_S 32
#define CHUNK_S  128

// ---------------------------------------------------------------- scratch
static __device__ __half g_Ahi[(size_t)MM * KK];
static __device__ __half g_Alo[(size_t)MM * KK];
static __device__ __half g_Wh [(size_t)NN * KK];    // column-permuted: e' = 4d+j
static __device__ float  g_ball[NN];                 // permuted bias
static __device__ float  g_q [(size_t)MM * DIM];
static __device__ float  g_kv[(size_t)MM * DIM];
static __device__ float  g_gs[(size_t)MM * DIM];
static __device__ float  g_part[BATCH * NCHUNK_S * DIM];

// ---------------------------------------------------------------- helpers
__device__ __forceinline__ uint32_t smem_u32(const void* p) {
    uint32_t a;
    asm("{ .reg .u64 t; cvta.to.shared.u64 t, %1; cvt.u32.u64 %0, t; }" : "=r"(a) : "l"(p));
    return a;
}

__device__ __forceinline__ void cp_async16(uint32_t smem_addr, const void* gptr) {
    asm volatile("cp.async.cg.shared.global [%0], [%1], 16;"
                 :: "r"(smem_addr), "l"(gptr) : "memory");
}
#define CP_COMMIT() asm volatile("cp.async.commit_group;" ::: "memory")
#define CP_WAIT1()  asm volatile("cp.async.wait_group 1;" ::: "memory")
#define CP_WAIT0()  asm volatile("cp.async.wait_group 0;" ::: "memory")

__device__ __forceinline__ void ldm_x4(uint32_t* r, uint32_t addr) {
    asm volatile("ldmatrix.sync.aligned.m8n8.x4.shared.b16 {%0,%1,%2,%3}, [%4];"
                 : "=r"(r[0]), "=r"(r[1]), "=r"(r[2]), "=r"(r[3]) : "r"(addr));
}

__device__ __forceinline__ void mma16816(float* c, const uint32_t* a, const uint32_t* b) {
    asm volatile(
        "mma.sync.aligned.m16n8k16.row.col.f32.f16.f16.f32 "
        "{%0,%1,%2,%3}, {%4,%5,%6,%7}, {%8,%9}, {%0,%1,%2,%3};"
        : "+f"(c[0]), "+f"(c[1]), "+f"(c[2]), "+f"(c[3])
        : "r"(a[0]), "r"(a[1]), "r"(a[2]), "r"(a[3]), "r"(b[0]), "r"(b[1]));
}

// ---------------------------------------------------------------- conversion
__global__ __launch_bounds__(256)
void conv_x_kernel(const float* __restrict__ x)
{
    size_t i = (size_t)blockIdx.x * 256 + threadIdx.x;   // float4 index
    float4 v = ((const float4*)x)[i];
    size_t o = i * 4;
    float a[4] = {v.x, v.y, v.z, v.w};
#pragma unroll
    for (int j = 0; j < 4; j++) {
        __half h = __float2half_rn(a[j]);
        __half l = __float2half_rn(a[j] - __half2float(h));
        g_Ahi[o + j] = h;
        g_Alo[o + j] = l;
    }
}

// Permuted W: destination column e' = 4d + j, j in {0:q, 1:k, 2:v, 3:gate}.
__global__ __launch_bounds__(256)
void conv_w_kernel(const float* __restrict__ Wqkv, const float* __restrict__ bqkv,
                   const float* __restrict__ Wg,   const float* __restrict__ bg)
{
    int ep = blockIdx.x;                 // [0, NN) permuted col
    int d  = ep >> 2;
    int j  = ep & 3;
    int t  = threadIdx.x;                // 256 threads -> KK/4 float4 per row
    const float* src = (j < 3) ? (Wqkv + (size_t)(j * DIM + d) * KK)
                               : (Wg + (size_t)d * KK);
    float4 v = ((const float4*)src)[t];
    size_t o = (size_t)ep * KK + t * 4;
    g_Wh[o + 0] = __float2half_rn(v.x);
    g_Wh[o + 1] = __float2half_rn(v.y);
    g_Wh[o + 2] = __float2half_rn(v.z);
    g_Wh[o + 3] = __float2half_rn(v.w);
    if (t == 0)
        g_ball[ep] = (j < 3) ? bqkv[j * DIM + d] : bg[d];
}

// ---------------------------------------------------------------- GEMM
// SMEM: padded tiles [128][40] fp16. Per stage: Ahi | Alo | B = 30720 B.
// 3 stages = 92160 B; epilogue reuses bytes [0,64K) as C tile + [64K,65K) red.
#define TPAD 40
#define TILE_B (128 * TPAD * 2)          // 10240
#define OFF_AHI 0
#define OFF_ALO (1 * TILE_B)
#define OFF_B   (2 * TILE_B)
#define STAGE_B (3 * TILE_B)             // 30720
#define NSTAGE 3
#define GEMM_SMEM (NSTAGE * STAGE_B)     // 92160

__device__ __forceinline__ void load_tile(uint32_t s_dst, const __half* g_src,
                                          int k0, int tid)
{
#pragma unroll
    for (int it = 0; it < 2; it++) {
        int c   = tid + it * 256;        // [0,512)
        int row = c >> 2;
        int kc  = c & 3;
        cp_async16(s_dst + (uint32_t)(row * (TPAD * 2) + kc * 16),
                   (const char*)(g_src + (size_t)row * KK + k0) + kc * 16);
    }
}

__global__ __launch_bounds__(256, 2)
void gemm_hmma_kernel()
{
    extern __shared__ char smem[];
    const uint32_t sb = smem_u32(smem);
    const int tid  = threadIdx.x;
    const int wid  = tid >> 5;
    const int lane = tid & 31;
    const int bm   = blockIdx.y;
    const int bn   = blockIdx.x;
    const int wM   = wid & 3;            // 0..3  (M warp, 32 rows)
    const int wN   = wid >> 2;           // 0..1  (N warp, 64 cols)

    const __half* Ahi = g_Ahi + (size_t)bm * BM * KK;
    const __half* Alo = g_Alo + (size_t)bm * BM * KK;
    const __half* Bh  = g_Wh  + (size_t)bn * BN * KK;

    float acc[2][8][4];                  // mi x ni x frag
#pragma unroll
    for (int i = 0; i < 2; i++)
#pragma unroll
        for (int j = 0; j < 8; j++)
#pragma unroll
            for (int r = 0; r < 4; r++) acc[i][j][r] = 0.0f;

    // ldmatrix lane addressing (verified R4-R7):
    // A row-major m x k: lanes 0-15 -> m rows @ k0; 16-31 -> same rows @ k8.
    const int aRow = wM * 32 + (lane & 15);
    const int aCol = (lane >> 4) * 8;
    // B [n][k] row-major, NON-trans ldmatrix.
    const int bRowN = wN * 64 + ((lane >> 4) * 8) + (lane & 7);
    const int bColK = ((lane >> 3) & 1) * 8;

    // ---- prologue: stages 0,1
    load_tile(sb + 0 * STAGE_B + OFF_AHI, Ahi, 0, tid);
    load_tile(sb + 0 * STAGE_B + OFF_ALO, Alo, 0, tid);
    load_tile(sb + 0 * STAGE_B + OFF_B,   Bh,  0, tid);
    CP_COMMIT();
    load_tile(sb + 1 * STAGE_B + OFF_AHI, Ahi, BK, tid);
    load_tile(sb + 1 * STAGE_B + OFF_ALO, Alo, BK, tid);
    load_tile(sb + 1 * STAGE_B + OFF_B,   Bh,  BK, tid);
    CP_COMMIT();

    int slot = 0, nslot = 2;
    for (int i = 0; i < KITERS; i++) {
        if (i < KITERS - 1) { CP_WAIT1(); } else { CP_WAIT0(); }
        __syncthreads();

        if (i + 2 < KITERS) {
            const uint32_t nb = sb + (uint32_t)nslot * STAGE_B;
            const int k0 = (i + 2) * BK;
            load_tile(nb + OFF_AHI, Ahi, k0, tid);
            load_tile(nb + OFF_ALO, Alo, k0, tid);
            load_tile(nb + OFF_B,   Bh,  k0, tid);
            CP_COMMIT();
        }

        const uint32_t cur = sb + (uint32_t)slot * STAGE_B;
#pragma unroll
        for (int ks = 0; ks < 2; ks++) {
            uint32_t ahi[2][4], alo[2][4], bf[8][2];
#pragma unroll
            for (int nh = 0; nh < 4; nh++) {
                uint32_t r[4];
                uint32_t boff = (uint32_t)((bRowN + nh * 16) * (TPAD * 2) +
                                           (ks * 16 + bColK) * 2);
                ldm_x4(r, cur + OFF_B + boff);
                bf[nh * 2 + 0][0] = r[0]; bf[nh * 2 + 0][1] = r[1];
                bf[nh * 2 + 1][0] = r[2]; bf[nh * 2 + 1][1] = r[3];
            }
#pragma unroll
            for (int mi = 0; mi < 2; mi++) {
                uint32_t aoff = (uint32_t)((aRow + mi * 16) * (TPAD * 2) +
                                           (ks * 16 + aCol) * 2);
                ldm_x4(ahi[mi], cur + OFF_AHI + aoff);
                ldm_x4(alo[mi], cur + OFF_ALO + aoff);
            }
#pragma unroll
            for (int mi = 0; mi < 2; mi++)
#pragma unroll
                for (int ni = 0; ni < 8; ni++)
                    mma16816(acc[mi][ni], ahi[mi], bf[ni]);
#pragma unroll
            for (int mi = 0; mi < 2; mi++)
#pragma unroll
                for (int ni = 0; ni < 8; ni++)
                    mma16816(acc[mi][ni], alo[mi], bf[ni]);
        }
        slot  = (slot == NSTAGE - 1) ? 0 : slot + 1;
        nslot = (nslot == NSTAGE - 1) ? 0 : nslot + 1;
    }

    // ---- fused epilogue ------------------------------------------------
    // Stage C tile (128x128 fp32, 64 KB) through smem, then each thread
    // processes 16 rows of one local dim: q,k,v,g -> q, kv, sigmoid(g),
    // plus the per-chunk partial sum of kv.
    __syncthreads();
    float* C = (float*)smem;
    const int g   = lane >> 2;
    const int tig = lane & 3;
#pragma unroll
    for (int mi = 0; mi < 2; mi++) {
#pragma unroll
        for (int ni = 0; ni < 8; ni++) {
            int col  = wN * 64 + ni * 8 + tig * 2;
            int row0 = wM * 32 + mi * 16 + g;
            C[row0 * 128 + col]           = acc[mi][ni][0];
            C[row0 * 128 + col + 1]       = acc[mi][ni][1];
            C[(row0 + 8) * 128 + col]     = acc[mi][ni][2];
            C[(row0 + 8) * 128 + col + 1] = acc[mi][ni][3];
        }
    }
    __syncthreads();

    const int dl = tid & 31;             // local dim 0..31
    const int rg = tid >> 5;             // row group 0..7 (16 rows each)
    const int dg = bn * 32 + dl;         // global dim
    const size_t m0 = (size_t)bm * BM;
    float4 bias = ((const float4*)g_ball)[bn * 32 + dl];
    float psum = 0.0f;
#pragma unroll 4
    for (int r = rg * 16; r < rg * 16 + 16; r++) {
        float4 c4 = ((const float4*)C)[r * 32 + dl];
        float qv = c4.x + bias.x;
        float kv = (c4.y + bias.y) * (c4.z + bias.z);
        float gt = c4.w + bias.w;
        float gs = 1.0f / (1.0f + __expf(-gt));
        size_t idx = (m0 + r) * DIM + dg;
        g_q [idx] = qv;
        g_kv[idx] = kv;
        g_gs[idx] = gs;
        psum += kv;
    }
    float* red = (float*)(smem + 65536);
    red[rg * 32 + dl] = psum;
    __syncthreads();
    if (tid < 32) {
        float s = 0.0f;
#pragma unroll
        for (int j = 0; j < 8; j++) s += red[j * 32 + tid];
        g_part[bm * DIM + bn * 32 + tid] = s;   // (b*32+c)*DIM == bm*DIM
    }
}

// ---------------------------------------------------------------- scan phases
__global__ __launch_bounds__(256)
void scan_part_kernel()
{
    const int idx = blockIdx.x * 256 + threadIdx.x;
    const int b = idx / DIM;
    const int d = idx % DIM;
    float ex = 0.0f;
#pragma unroll
    for (int c = 0; c < NCHUNK_S; c++) {
        float t = g_part[(b * NCHUNK_S + c) * DIM + d];
        g_part[(b * NCHUNK_S + c) * DIM + d] = ex;
        ex += t;
    }
}

__global__ __launch_bounds__(256)
void final_kernel(float* __restrict__ out)
{
    const int d = blockIdx.x * 256 + threadIdx.x;
    const int c = blockIdx.y;
    const int b = blockIdx.z;
    float acc = g_part[(b * NCHUNK_S + c) * DIM + d];
    const size_t m0 = (size_t)(b * SEQ + c * CHUNK_S);
#pragma unroll 4
    for (int i = 0; i < CHUNK_S; i++) {
        size_t idx = (m0 + i) * DIM + d;
        acc += g_kv[idx];
        out[idx] = g_q[idx] * acc * g_gs[idx];
    }
}

// ---------------------------------------------------------------- launch
extern "C" void kernel_launch(void* const* d_in, const int* in_sizes, int n_in,
                              void* d_out, int out_size)
{
    const float* x    = (const float*)d_in[0];
    const float* Wqkv = (const float*)d_in[1];
    const float* bqkv = (const float*)d_in[2];
    const float* Wg   = (const float*)d_in[3];
    const float* bg   = (const float*)d_in[4];
    float* out        = (float*)d_out;

    conv_x_kernel<<<(MM * KK / 4) / 256, 256>>>(x);
    conv_w_kernel<<<NN, 256>>>(Wqkv, bqkv, Wg, bg);

    cudaFuncSetAttribute(gemm_hmma_kernel,
                         cudaFuncAttributeMaxDynamicSharedMemorySize, GEMM_SMEM);
    dim3 ggrid(NN / BN, MM / BM);          // (32, 128)
    gemm_hmma_kernel<<<ggrid, 256, GEMM_SMEM>>>();

    scan_part_kernel<<<(BATCH * DIM) / 256, 256>>>();
    dim3 fgrid(DIM / 256, NCHUNK_S, BATCH);
    final_kernel<<<fgrid, 256>>>(out);
}

// round 9
// speedup vs baseline: 1.7464x; 1.6264x over previous
#include <cuda_runtime.h>
#include <cuda_fp16.h>
#include <cstdint>

// ---------------------------------------------------------------- shapes
#define BATCH 4
#define SEQ   4096
#define DIM   1024
#define MM    (BATCH * SEQ)   // 16384
#define KK    DIM             // 1024
#define NN    (4 * DIM)       // 4096 : interleaved [q k v g] per dim

// GEMM tiling
#define BM 128
#define BN 128
#define BK 32
#define KITERS (KK / BK)      // 32
// scan chunking: one GEMM M-block == one chunk
#define NCHUNK_S 32
#define CHUNK_S  128

// ---------------------------------------------------------------- scratch
static __device__ __half g_Ah[(size_t)MM * KK];
static __device__ __half g_Wh[(size_t)NN * KK];     // column-permuted: e' = 4d+j
static __device__ float  g_ball[NN];                 // permuted bias
static __device__ float  g_q [(size_t)MM * DIM];
static __device__ float  g_kv[(size_t)MM * DIM];
static __device__ float  g_gs[(size_t)MM * DIM];
static __device__ float  g_part[BATCH * NCHUNK_S * DIM];

// ---------------------------------------------------------------- helpers
__device__ __forceinline__ uint32_t smem_u32(const void* p) {
    uint32_t a;
    asm("{ .reg .u64 t; cvta.to.shared.u64 t, %1; cvt.u32.u64 %0, t; }" : "=r"(a) : "l"(p));
    return a;
}

__device__ __forceinline__ void cp_async16(uint32_t smem_addr, const void* gptr) {
    asm volatile("cp.async.cg.shared.global [%0], [%1], 16;"
                 :: "r"(smem_addr), "l"(gptr) : "memory");
}
#define CP_COMMIT() asm volatile("cp.async.commit_group;" ::: "memory")
#define CP_WAIT1()  asm volatile("cp.async.wait_group 1;" ::: "memory")
#define CP_WAIT0()  asm volatile("cp.async.wait_group 0;" ::: "memory")

__device__ __forceinline__ void ldm_x4(uint32_t* r, uint32_t addr) {
    asm volatile("ldmatrix.sync.aligned.m8n8.x4.shared.b16 {%0,%1,%2,%3}, [%4];"
                 : "=r"(r[0]), "=r"(r[1]), "=r"(r[2]), "=r"(r[3]) : "r"(addr));
}

__device__ __forceinline__ void mma16816(float* c, const uint32_t* a, const uint32_t* b) {
    asm volatile(
        "mma.sync.aligned.m16n8k16.row.col.f32.f16.f16.f32 "
        "{%0,%1,%2,%3}, {%4,%5,%6,%7}, {%8,%9}, {%0,%1,%2,%3};"
        : "+f"(c[0]), "+f"(c[1]), "+f"(c[2]), "+f"(c[3])
        : "r"(a[0]), "r"(a[1]), "r"(a[2]), "r"(a[3]), "r"(b[0]), "r"(b[1]));
}

// ---------------------------------------------------------------- conversion
__global__ __launch_bounds__(256)
void conv_x_kernel(const float* __restrict__ x)
{
    size_t i = (size_t)blockIdx.x * 256 + threadIdx.x;   // float4 index
    float4 v = ((const float4*)x)[i];
    size_t o = i * 4;
    g_Ah[o + 0] = __float2half_rn(v.x);
    g_Ah[o + 1] = __float2half_rn(v.y);
    g_Ah[o + 2] = __float2half_rn(v.z);
    g_Ah[o + 3] = __float2half_rn(v.w);
}

// Permuted W: destination column e' = 4d + j, j in {0:q, 1:k, 2:v, 3:gate}.
__global__ __launch_bounds__(256)
void conv_w_kernel(const float* __restrict__ Wqkv, const float* __restrict__ bqkv,
                   const float* __restrict__ Wg,   const float* __restrict__ bg)
{
    int ep = blockIdx.x;                 // [0, NN) permuted col
    int d  = ep >> 2;
    int j  = ep & 3;
    int t  = threadIdx.x;                // 256 threads -> KK/4 float4 per row
    const float* src = (j < 3) ? (Wqkv + (size_t)(j * DIM + d) * KK)
                               : (Wg + (size_t)d * KK);
    float4 v = ((const float4*)src)[t];
    size_t o = (size_t)ep * KK + t * 4;
    g_Wh[o + 0] = __float2half_rn(v.x);
    g_Wh[o + 1] = __float2half_rn(v.y);
    g_Wh[o + 2] = __float2half_rn(v.z);
    g_Wh[o + 3] = __float2half_rn(v.w);
    if (t == 0)
        g_ball[ep] = (j < 3) ? bqkv[j * DIM + d] : bg[d];
}

// ---------------------------------------------------------------- GEMM
// SMEM: padded tiles [128][40] fp16. Per stage: A | B = 20480 B.
// 3 stages = 61440 B; epilogue reuses [0,64K) as C tile + [64K,65K) red.
#define TPAD 40
#define TILE_B (128 * TPAD * 2)          // 10240
#define OFF_A 0
#define OFF_B (TILE_B)
#define STAGE_B (2 * TILE_B)             // 20480
#define NSTAGE 3
#define GEMM_SMEM (65536 + 1024)         // 66560 (>= 3*STAGE_B = 61440)

__device__ __forceinline__ void load_tile(uint32_t s_dst, const __half* g_src,
                                          int k0, int tid)
{
#pragma unroll
    for (int it = 0; it < 2; it++) {
        int c   = tid + it * 256;        // [0,512)
        int row = c >> 2;
        int kc  = c & 3;
        cp_async16(s_dst + (uint32_t)(row * (TPAD * 2) + kc * 16),
                   (const char*)(g_src + (size_t)row * KK + k0) + kc * 16);
    }
}

__global__ __launch_bounds__(256, 2)
void gemm_hmma_kernel()
{
    extern __shared__ char smem[];
    const uint32_t sb = smem_u32(smem);
    const int tid  = threadIdx.x;
    const int wid  = tid >> 5;
    const int lane = tid & 31;
    const int bm   = blockIdx.y;
    const int bn   = blockIdx.x;
    const int wM   = wid & 3;            // 0..3  (M warp, 32 rows)
    const int wN   = wid >> 2;           // 0..1  (N warp, 64 cols)

    const __half* Ah = g_Ah + (size_t)bm * BM * KK;
    const __half* Bh = g_Wh + (size_t)bn * BN * KK;

    float acc[2][8][4];                  // mi x ni x frag
#pragma unroll
    for (int i = 0; i < 2; i++)
#pragma unroll
        for (int j = 0; j < 8; j++)
#pragma unroll
            for (int r = 0; r < 4; r++) acc[i][j][r] = 0.0f;

    // ldmatrix lane addressing (verified R4-R8):
    const int aRow = wM * 32 + (lane & 15);
    const int aCol = (lane >> 4) * 8;
    const int bRowN = wN * 64 + ((lane >> 4) * 8) + (lane & 7);
    const int bColK = ((lane >> 3) & 1) * 8;

    // ---- prologue: stages 0,1
    load_tile(sb + 0 * STAGE_B + OFF_A, Ah, 0, tid);
    load_tile(sb + 0 * STAGE_B + OFF_B, Bh, 0, tid);
    CP_COMMIT();
    load_tile(sb + 1 * STAGE_B + OFF_A, Ah, BK, tid);
    load_tile(sb + 1 * STAGE_B + OFF_B, Bh, BK, tid);
    CP_COMMIT();

    int slot = 0, nslot = 2;
    for (int i = 0; i < KITERS; i++) {
        if (i < KITERS - 1) { CP_WAIT1(); } else { CP_WAIT0(); }
        __syncthreads();

        if (i + 2 < KITERS) {
            const uint32_t nb = sb + (uint32_t)nslot * STAGE_B;
            const int k0 = (i + 2) * BK;
            load_tile(nb + OFF_A, Ah, k0, tid);
            load_tile(nb + OFF_B, Bh, k0, tid);
            CP_COMMIT();
        }

        const uint32_t cur = sb + (uint32_t)slot * STAGE_B;
#pragma unroll
        for (int ks = 0; ks < 2; ks++) {
            uint32_t af[2][4], bf[8][2];
#pragma unroll
            for (int nh = 0; nh < 4; nh++) {
                uint32_t r[4];
                uint32_t boff = (uint32_t)((bRowN + nh * 16) * (TPAD * 2) +
                                           (ks * 16 + bColK) * 2);
                ldm_x4(r, cur + OFF_B + boff);
                bf[nh * 2 + 0][0] = r[0]; bf[nh * 2 + 0][1] = r[1];
                bf[nh * 2 + 1][0] = r[2]; bf[nh * 2 + 1][1] = r[3];
            }
#pragma unroll
            for (int mi = 0; mi < 2; mi++) {
                uint32_t aoff = (uint32_t)((aRow + mi * 16) * (TPAD * 2) +
                                           (ks * 16 + aCol) * 2);
                ldm_x4(af[mi], cur + OFF_A + aoff);
            }
#pragma unroll
            for (int mi = 0; mi < 2; mi++)
#pragma unroll
                for (int ni = 0; ni < 8; ni++)
                    mma16816(acc[mi][ni], af[mi], bf[ni]);
        }
        slot  = (slot == NSTAGE - 1) ? 0 : slot + 1;
        nslot = (nslot == NSTAGE - 1) ? 0 : nslot + 1;
    }

    // ---- fused epilogue ------------------------------------------------
    __syncthreads();
    float* C = (float*)smem;
    const int g   = lane >> 2;
    const int tig = lane & 3;
#pragma unroll
    for (int mi = 0; mi < 2; mi++) {
#pragma unroll
        for (int ni = 0; ni < 8; ni++) {
            int col  = wN * 64 + ni * 8 + tig * 2;
            int row0 = wM * 32 + mi * 16 + g;
            C[row0 * 128 + col]           = acc[mi][ni][0];
            C[row0 * 128 + col + 1]       = acc[mi][ni][1];
            C[(row0 + 8) * 128 + col]     = acc[mi][ni][2];
            C[(row0 + 8) * 128 + col + 1] = acc[mi][ni][3];
        }
    }
    __syncthreads();

    const int dl = tid & 31;             // local dim 0..31
    const int rg = tid >> 5;             // row group 0..7 (16 rows each)
    const int dg = bn * 32 + dl;         // global dim
    const size_t m0 = (size_t)bm * BM;
    float4 bias = ((const float4*)g_ball)[bn * 32 + dl];
    float psum = 0.0f;
#pragma unroll 4
    for (int r = rg * 16; r < rg * 16 + 16; r++) {
        float4 c4 = ((const float4*)C)[r * 32 + dl];
        float qv = c4.x + bias.x;
        float kv = (c4.y + bias.y) * (c4.z + bias.z);
        float gt = c4.w + bias.w;
        float gs = 1.0f / (1.0f + __expf(-gt));
        size_t idx = (m0 + r) * DIM + dg;
        g_q [idx] = qv;
        g_kv[idx] = kv;
        g_gs[idx] = gs;
        psum += kv;
    }
    float* red = (float*)(smem + 65536);
    red[rg * 32 + dl] = psum;
    __syncthreads();
    if (tid < 32) {
        float s = 0.0f;
#pragma unroll
        for (int j = 0; j < 8; j++) s += red[j * 32 + tid];
        g_part[bm * DIM + bn * 32 + tid] = s;   // (b*32+c)*DIM == bm*DIM
    }
}

// ---------------------------------------------------------------- scan phases
__global__ __launch_bounds__(256)
void scan_part_kernel()
{
    const int idx = blockIdx.x * 256 + threadIdx.x;
    const int b = idx / DIM;
    const int d = idx % DIM;
    float ex = 0.0f;
#pragma unroll
    for (int c = 0; c < NCHUNK_S; c++) {
        float t = g_part[(b * NCHUNK_S + c) * DIM + d];
        g_part[(b * NCHUNK_S + c) * DIM + d] = ex;
        ex += t;
    }
}

__global__ __launch_bounds__(256)
void final_kernel(float* __restrict__ out)
{
    const int d = blockIdx.x * 256 + threadIdx.x;
    const int c = blockIdx.y;
    const int b = blockIdx.z;
    float acc = g_part[(b * NCHUNK_S + c) * DIM + d];
    const size_t m0 = (size_t)(b * SEQ + c * CHUNK_S);
#pragma unroll 4
    for (int i = 0; i < CHUNK_S; i++) {
        size_t idx = (m0 + i) * DIM + d;
        acc += g_kv[idx];
        out[idx] = g_q[idx] * acc * g_gs[idx];
    }
}

// ---------------------------------------------------------------- launch
extern "C" void kernel_launch(void* const* d_in, const int* in_sizes, int n_in,
                              void* d_out, int out_size)
{
    const float* x    = (const float*)d_in[0];
    const float* Wqkv = (const float*)d_in[1];
    const float* bqkv = (const float*)d_in[2];
    const float* Wg   = (const float*)d_in[3];
    const float* bg   = (const float*)d_in[4];
    float* out        = (float*)d_out;

    conv_x_kernel<<<(MM * KK / 4) / 256, 256>>>(x);
    conv_w_kernel<<<NN, 256>>>(Wqkv, bqkv, Wg, bg);

    cudaFuncSetAttribute(gemm_hmma_kernel,
                         cudaFuncAttributeMaxDynamicSharedMemorySize, GEMM_SMEM);
    dim3 ggrid(NN / BN, MM / BM);          // (32, 128)
    gemm_hmma_kernel<<<ggrid, 256, GEMM_SMEM>>>();

    scan_part_kernel<<<(BATCH * DIM) / 256, 256>>>();
    dim3 fgrid(DIM / 256, NCHUNK_S, BATCH);
    final_kernel<<<fgrid, 256>>>(out);
}

// round 10
// speedup vs baseline: 1.7884x; 1.0241x over previous
#include <cuda_runtime.h>
#include <cuda_fp16.h>
#include <cstdint>

// ---------------------------------------------------------------- shapes
#define BATCH 4
#define SEQ   4096
#define DIM   1024
#define MM    (BATCH * SEQ)   // 16384
#define KK    DIM             // 1024
#define NN    (4 * DIM)       // 4096 : interleaved [q k v g] per dim

// GEMM tiling
#define BM 128
#define BN 128
#define BK 32
#define KITERS (KK / BK)      // 32
#define NBM (MM / BM)         // 128  (= 4 batches x 32 chunks)
#define NBN (NN / BN)         // 32

// ---------------------------------------------------------------- scratch
static __device__ __half g_Ah[(size_t)MM * KK];
static __device__ __half g_Wh[(size_t)NN * KK];     // column-permuted: e' = 4d+j
static __device__ float  g_ball[NN];                 // permuted bias
static __device__ float          g_pref[(size_t)NBM * DIM];  // inclusive chunk prefixes
static __device__ unsigned int   g_flag[NBM * NBN];          // publication flags

// ---------------------------------------------------------------- helpers
__device__ __forceinline__ uint32_t smem_u32(const void* p) {
    uint32_t a;
    asm("{ .reg .u64 t; cvta.to.shared.u64 t, %1; cvt.u32.u64 %0, t; }" : "=r"(a) : "l"(p));
    return a;
}

__device__ __forceinline__ void cp_async16(uint32_t smem_addr, const void* gptr) {
    asm volatile("cp.async.cg.shared.global [%0], [%1], 16;"
                 :: "r"(smem_addr), "l"(gptr) : "memory");
}
#define CP_COMMIT() asm volatile("cp.async.commit_group;" ::: "memory")
#define CP_WAIT1()  asm volatile("cp.async.wait_group 1;" ::: "memory")
#define CP_WAIT0()  asm volatile("cp.async.wait_group 0;" ::: "memory")

__device__ __forceinline__ void ldm_x4(uint32_t* r, uint32_t addr) {
    asm volatile("ldmatrix.sync.aligned.m8n8.x4.shared.b16 {%0,%1,%2,%3}, [%4];"
                 : "=r"(r[0]), "=r"(r[1]), "=r"(r[2]), "=r"(r[3]) : "r"(addr));
}

__device__ __forceinline__ void mma16816(float* c, const uint32_t* a, const uint32_t* b) {
    asm volatile(
        "mma.sync.aligned.m16n8k16.row.col.f32.f16.f16.f32 "
        "{%0,%1,%2,%3}, {%4,%5,%6,%7}, {%8,%9}, {%0,%1,%2,%3};"
        : "+f"(c[0]), "+f"(c[1]), "+f"(c[2]), "+f"(c[3])
        : "r"(a[0]), "r"(a[1]), "r"(a[2]), "r"(a[3]), "r"(b[0]), "r"(b[1]));
}

// ---------------------------------------------------------------- setup
__global__ __launch_bounds__(256)
void zero_flags_kernel()
{
    g_flag[blockIdx.x * 256 + threadIdx.x] = 0u;
}

__global__ __launch_bounds__(256)
void conv_x_kernel(const float* __restrict__ x)
{
    size_t i = (size_t)blockIdx.x * 256 + threadIdx.x;   // float4 index
    float4 v = ((const float4*)x)[i];
    size_t o = i * 4;
    g_Ah[o + 0] = __float2half_rn(v.x);
    g_Ah[o + 1] = __float2half_rn(v.y);
    g_Ah[o + 2] = __float2half_rn(v.z);
    g_Ah[o + 3] = __float2half_rn(v.w);
}

// Permuted W: destination column e' = 4d + j, j in {0:q, 1:k, 2:v, 3:gate}.
__global__ __launch_bounds__(256)
void conv_w_kernel(const float* __restrict__ Wqkv, const float* __restrict__ bqkv,
                   const float* __restrict__ Wg,   const float* __restrict__ bg)
{
    int ep = blockIdx.x;                 // [0, NN) permuted col
    int d  = ep >> 2;
    int j  = ep & 3;
    int t  = threadIdx.x;                // 256 threads -> KK/4 float4 per row
    const float* src = (j < 3) ? (Wqkv + (size_t)(j * DIM + d) * KK)
                               : (Wg + (size_t)d * KK);
    float4 v = ((const float4*)src)[t];
    size_t o = (size_t)ep * KK + t * 4;
    g_Wh[o + 0] = __float2half_rn(v.x);
    g_Wh[o + 1] = __float2half_rn(v.y);
    g_Wh[o + 2] = __float2half_rn(v.z);
    g_Wh[o + 3] = __float2half_rn(v.w);
    if (t == 0)
        g_ball[ep] = (j < 3) ? bqkv[j * DIM + d] : bg[d];
}

// ---------------------------------------------------------------- GEMM + fused scan
// SMEM: mainloop uses 3 stages x (A|B) = 61440 B.
// Epilogue reuses [0,64K) as C tile; [64K, 64K+1024) red; [+1024, +1152) red2.
#define TPAD 40
#define TILE_B (128 * TPAD * 2)          // 10240
#define OFF_A 0
#define OFF_B (TILE_B)
#define STAGE_B (2 * TILE_B)             // 20480
#define NSTAGE 3
#define GEMM_SMEM (65536 + 1024 + 128)   // 66688

__device__ __forceinline__ void load_tile(uint32_t s_dst, const __half* g_src,
                                          int k0, int tid)
{
#pragma unroll
    for (int it = 0; it < 2; it++) {
        int c   = tid + it * 256;        // [0,512)
        int row = c >> 2;
        int kc  = c & 3;
        cp_async16(s_dst + (uint32_t)(row * (TPAD * 2) + kc * 16),
                   (const char*)(g_src + (size_t)row * KK + k0) + kc * 16);
    }
}

__global__ __launch_bounds__(256, 2)
void gemm_fused_kernel(float* __restrict__ out)
{
    extern __shared__ char smem[];
    const uint32_t sb = smem_u32(smem);
    const int tid  = threadIdx.x;
    const int wid  = tid >> 5;
    const int lane = tid & 31;
    const int bm   = blockIdx.y;
    const int bn   = blockIdx.x;
    const int wM   = wid & 3;            // 0..3  (M warp, 32 rows)
    const int wN   = wid >> 2;           // 0..1  (N warp, 64 cols)

    const __half* Ah = g_Ah + (size_t)bm * BM * KK;
    const __half* Bh = g_Wh + (size_t)bn * BN * KK;

    float acc[2][8][4];                  // mi x ni x frag
#pragma unroll
    for (int i = 0; i < 2; i++)
#pragma unroll
        for (int j = 0; j < 8; j++)
#pragma unroll
            for (int r = 0; r < 4; r++) acc[i][j][r] = 0.0f;

    // ldmatrix lane addressing (verified R4-R9):
    const int aRow = wM * 32 + (lane & 15);
    const int aCol = (lane >> 4) * 8;
    const int bRowN = wN * 64 + ((lane >> 4) * 8) + (lane & 7);
    const int bColK = ((lane >> 3) & 1) * 8;

    // ---- prologue: stages 0,1
    load_tile(sb + 0 * STAGE_B + OFF_A, Ah, 0, tid);
    load_tile(sb + 0 * STAGE_B + OFF_B, Bh, 0, tid);
    CP_COMMIT();
    load_tile(sb + 1 * STAGE_B + OFF_A, Ah, BK, tid);
    load_tile(sb + 1 * STAGE_B + OFF_B, Bh, BK, tid);
    CP_COMMIT();

    int slot = 0, nslot = 2;
    for (int i = 0; i < KITERS; i++) {
        if (i < KITERS - 1) { CP_WAIT1(); } else { CP_WAIT0(); }
        __syncthreads();

        if (i + 2 < KITERS) {
            const uint32_t nb = sb + (uint32_t)nslot * STAGE_B;
            const int k0 = (i + 2) * BK;
            load_tile(nb + OFF_A, Ah, k0, tid);
            load_tile(nb + OFF_B, Bh, k0, tid);
            CP_COMMIT();
        }

        const uint32_t cur = sb + (uint32_t)slot * STAGE_B;
#pragma unroll
        for (int ks = 0; ks < 2; ks++) {
            uint32_t af[2][4], bf[8][2];
#pragma unroll
            for (int nh = 0; nh < 4; nh++) {
                uint32_t r[4];
                uint32_t boff = (uint32_t)((bRowN + nh * 16) * (TPAD * 2) +
                                           (ks * 16 + bColK) * 2);
                ldm_x4(r, cur + OFF_B + boff);
                bf[nh * 2 + 0][0] = r[0]; bf[nh * 2 + 0][1] = r[1];
                bf[nh * 2 + 1][0] = r[2]; bf[nh * 2 + 1][1] = r[3];
            }
#pragma unroll
            for (int mi = 0; mi < 2; mi++) {
                uint32_t aoff = (uint32_t)((aRow + mi * 16) * (TPAD * 2) +
                                           (ks * 16 + aCol) * 2);
                ldm_x4(af[mi], cur + OFF_A + aoff);
            }
#pragma unroll
            for (int mi = 0; mi < 2; mi++)
#pragma unroll
                for (int ni = 0; ni < 8; ni++)
                    mma16816(acc[mi][ni], af[mi], bf[ni]);
        }
        slot  = (slot == NSTAGE - 1) ? 0 : slot + 1;
        nslot = (nslot == NSTAGE - 1) ? 0 : nslot + 1;
    }

    // ---- fused epilogue with decoupled chained scan --------------------
    __syncthreads();
    float* C = (float*)smem;
    const int g   = lane >> 2;
    const int tig = lane & 3;
#pragma unroll
    for (int mi = 0; mi < 2; mi++) {
#pragma unroll
        for (int ni = 0; ni < 8; ni++) {
            int col  = wN * 64 + ni * 8 + tig * 2;
            int row0 = wM * 32 + mi * 16 + g;
            C[row0 * 128 + col]           = acc[mi][ni][0];
            C[row0 * 128 + col + 1]       = acc[mi][ni][1];
            C[(row0 + 8) * 128 + col]     = acc[mi][ni][2];
            C[(row0 + 8) * 128 + col + 1] = acc[mi][ni][3];
        }
    }
    __syncthreads();

    const int dl = tid & 31;             // local dim 0..31
    const int rg = tid >> 5;             // row group 0..7 (16 rows each)
    const int dg = bn * 32 + dl;         // global dim
    float4 bias = ((const float4*)g_ball)[dg];

    // pass 1: transform (q,k,v,g) -> (qg, kv) in place, accumulate kv sum
    float psum = 0.0f;
#pragma unroll 4
    for (int r = rg * 16; r < rg * 16 + 16; r++) {
        float4 c4 = ((const float4*)C)[r * 32 + dl];
        float qv = c4.x + bias.x;
        float kv = (c4.y + bias.y) * (c4.z + bias.z);
        float gt = c4.w + bias.w;
        float gs = 1.0f / (1.0f + __expf(-gt));
        ((float4*)C)[r * 32 + dl] = make_float4(qv * gs, kv, 0.0f, 0.0f);
        psum += kv;
    }
    float* red  = (float*)(smem + 65536);        // 256 floats
    float* red2 = (float*)(smem + 65536 + 1024); // 32 floats
    red[rg * 32 + dl] = psum;
    __syncthreads();

    // chained scan across chunks (bm within same batch of 32)
    if (tid < 32) {
        const int d = tid;
        float ex = 0.0f;
#pragma unroll
        for (int j = 0; j < 8; j++) {
            float t = red[j * 32 + d];
            red[j * 32 + d] = ex;        // exclusive group offset
            ex += t;
        }
        float P = 0.0f;
        if ((bm & 31) != 0) {
            volatile unsigned int* fl = &g_flag[(bm - 1) * NBN + bn];
            while (*fl == 0u) __nanosleep(40);
            __threadfence();
            P = g_pref[(size_t)(bm - 1) * DIM + bn * 32 + d];
        }
        red2[d] = P;
        g_pref[(size_t)bm * DIM + bn * 32 + d] = P + ex;
        __threadfence();
    }
    __syncthreads();
    if (tid == 0) {
        __threadfence();
        atomicExch(&g_flag[bm * NBN + bn], 1u);
    }

    // pass 2: running cumsum + output
    float racc = red2[dl] + red[rg * 32 + dl];
    const size_t m0 = (size_t)bm * BM;
#pragma unroll 4
    for (int r = rg * 16; r < rg * 16 + 16; r++) {
        float4 c4 = ((const float4*)C)[r * 32 + dl];
        racc += c4.y;
        out[(m0 + r) * DIM + dg] = c4.x * racc;
    }
}

// ---------------------------------------------------------------- launch
extern "C" void kernel_launch(void* const* d_in, const int* in_sizes, int n_in,
                              void* d_out, int out_size)
{
    const float* x    = (const float*)d_in[0];
    const float* Wqkv = (const float*)d_in[1];
    const float* bqkv = (const float*)d_in[2];
    const float* Wg   = (const float*)d_in[3];
    const float* bg   = (const float*)d_in[4];
    float* out        = (float*)d_out;

    zero_flags_kernel<<<(NBM * NBN) / 256, 256>>>();
    conv_x_kernel<<<(MM * KK / 4) / 256, 256>>>(x);
    conv_w_kernel<<<NN, 256>>>(Wqkv, bqkv, Wg, bg);

    cudaFuncSetAttribute(gemm_fused_kernel,
                         cudaFuncAttributeMaxDynamicSharedMemorySize, GEMM_SMEM);
    dim3 ggrid(NBN, NBM);                  // (32, 128), bn minor -> bm-1 earlier
    gemm_fused_kernel<<<ggrid, 256, GEMM_SMEM>>>(out);
}